// round 1
// baseline (speedup 1.0000x reference)
#include <cuda_runtime.h>
#include <math.h>

#define BDIM 4096
#define DDIM 1024
#define KSEL 1024
#define EPSV 1e-6f
#define MARGINV 0.5f
#define BIGV 1.0e6f

// Scratch (device globals — allocation-free per harness rules)
__device__ float g_dist[(size_t)BDIM * BDIM];   // 64 MB
__device__ float g_distT[(size_t)BDIM * BDIM];  // 64 MB
__device__ float g_nx[BDIM];
__device__ float g_ny[BDIM];
__device__ float g_rl[2 * BDIM];

// ---------------------------------------------------------------------------
// Row norms: nx[i] = ||x_i + eps||^2,  ny[j] = ||y_j||^2
// grid (BDIM, 2), 256 threads
// ---------------------------------------------------------------------------
__global__ void norms_kernel(const float* __restrict__ X, const float* __restrict__ Y) {
    __shared__ float sm[256];
    const int row = blockIdx.x;
    const int isY = blockIdx.y;
    const float* p = (isY ? Y : X) + (size_t)row * DDIM;
    const float eps = isY ? 0.0f : EPSV;
    float s = 0.0f;
    for (int i = threadIdx.x; i < DDIM; i += 256) {
        float v = p[i] + eps;
        s += v * v;
    }
    sm[threadIdx.x] = s;
    __syncthreads();
    for (int off = 128; off; off >>= 1) {
        if (threadIdx.x < off) sm[threadIdx.x] += sm[threadIdx.x + off];
        __syncthreads();
    }
    if (threadIdx.x == 0) {
        if (isY) g_ny[row] = sm[0];
        else     g_nx[row] = sm[0];
    }
}

// ---------------------------------------------------------------------------
// GEMM + distance epilogue:
//   dist[i][j] = sqrt(max(nx[i] + ny[j] - 2 * (x_i+eps)·y_j, 0))
// 128x128 block tile, BK=16, 256 threads, 8x8 per thread (strided 16 layout).
// grid (32, 32)
// ---------------------------------------------------------------------------
__global__ void __launch_bounds__(256) gemm_dist_kernel(const float* __restrict__ X,
                                                        const float* __restrict__ Y) {
    __shared__ float As[16][128];
    __shared__ float Bs[16][128];
    const int bi = blockIdx.y * 128;
    const int bj = blockIdx.x * 128;
    const int tid = threadIdx.x;
    const int tx = tid & 15;   // column group
    const int ty = tid >> 4;   // row group

    float acc[8][8];
#pragma unroll
    for (int m = 0; m < 8; m++)
#pragma unroll
        for (int n = 0; n < 8; n++) acc[m][n] = 0.0f;

    for (int k0 = 0; k0 < DDIM; k0 += 16) {
        // Cooperative load: 128 rows x 16 cols for each of A, B. 2 float4 per thread.
#pragma unroll
        for (int l = 0; l < 2; l++) {
            int idx = tid + l * 256;          // 0..511
            int r = idx >> 2;                 // 0..127
            int c4 = (idx & 3) * 4;           // 0,4,8,12
            float4 va = *(const float4*)(X + (size_t)(bi + r) * DDIM + k0 + c4);
            As[c4 + 0][r] = va.x + EPSV;
            As[c4 + 1][r] = va.y + EPSV;
            As[c4 + 2][r] = va.z + EPSV;
            As[c4 + 3][r] = va.w + EPSV;
            float4 vb = *(const float4*)(Y + (size_t)(bj + r) * DDIM + k0 + c4);
            Bs[c4 + 0][r] = vb.x;
            Bs[c4 + 1][r] = vb.y;
            Bs[c4 + 2][r] = vb.z;
            Bs[c4 + 3][r] = vb.w;
        }
        __syncthreads();
#pragma unroll
        for (int k = 0; k < 16; k++) {
            float a[8], b[8];
#pragma unroll
            for (int m = 0; m < 8; m++) a[m] = As[k][m * 16 + ty];
#pragma unroll
            for (int n = 0; n < 8; n++) b[n] = Bs[k][n * 16 + tx];
#pragma unroll
            for (int m = 0; m < 8; m++)
#pragma unroll
                for (int n = 0; n < 8; n++) acc[m][n] += a[m] * b[n];
        }
        __syncthreads();
    }

    // Epilogue: convert dot products to distances and store
    float nxv[8], nyv[8];
#pragma unroll
    for (int m = 0; m < 8; m++) nxv[m] = g_nx[bi + m * 16 + ty];
#pragma unroll
    for (int n = 0; n < 8; n++) nyv[n] = g_ny[bj + n * 16 + tx];

#pragma unroll
    for (int m = 0; m < 8; m++) {
        const int row = bi + m * 16 + ty;
        float* dp = g_dist + (size_t)row * BDIM + bj;
#pragma unroll
        for (int n = 0; n < 8; n++) {
            float sq = nxv[m] + nyv[n] - 2.0f * acc[m][n];
            dp[n * 16 + tx] = sqrtf(fmaxf(sq, 0.0f));
        }
    }
}

// ---------------------------------------------------------------------------
// Transpose dist -> distT (32x32 smem tiles), grid (128,128), block (32,8)
// ---------------------------------------------------------------------------
__global__ void transpose_kernel() {
    __shared__ float tile[32][33];
    int x = blockIdx.x * 32 + threadIdx.x;
    int y = blockIdx.y * 32 + threadIdx.y;
#pragma unroll
    for (int j = 0; j < 32; j += 8)
        tile[threadIdx.y + j][threadIdx.x] = g_dist[(size_t)(y + j) * BDIM + x];
    __syncthreads();
    x = blockIdx.y * 32 + threadIdx.x;
    y = blockIdx.x * 32 + threadIdx.y;
#pragma unroll
    for (int j = 0; j < 32; j += 8)
        g_distT[(size_t)(y + j) * BDIM + x] = tile[threadIdx.x][threadIdx.y + j];
}

// ---------------------------------------------------------------------------
// Per-row loss with exact K-th order statistic (4-pass radix select on float
// bit patterns — valid since all values are non-negative).
// grid (BDIM, 2): y=0 uses dist rows (loss_xy), y=1 uses distT rows (loss_yx).
// 256 threads per row.
// ---------------------------------------------------------------------------
__global__ void __launch_bounds__(256) select_kernel() {
    __shared__ float vals[BDIM];      // 16 KB
    __shared__ unsigned hist[256];
    __shared__ float red_f[256];
    __shared__ unsigned red_u[256];
    __shared__ float s_t;
    __shared__ unsigned s_prefix, s_remk;

    const int row = blockIdx.x;
    const int tid = threadIdx.x;
    const float* mat = blockIdx.y ? g_distT : g_dist;
    float* rl = g_rl + blockIdx.y * BDIM;
    const float* rp = mat + (size_t)row * BDIM;

    for (int i = tid; i < BDIM; i += 256) vals[i] = rp[i];
    __syncthreads();
    if (tid == 0) {
        s_t = MARGINV + vals[row];   // t = margin + pos (diagonal)
        vals[row] = BIGV;            // exclude diagonal from negatives
    }
    __syncthreads();
    const float t = s_t;

    // Count c = #{d < t} and full hinge sum
    unsigned c = 0;
    float s = 0.0f;
    for (int i = tid; i < BDIM; i += 256) {
        float v = vals[i];
        if (v < t) { c++; s += t - v; }
    }
    red_u[tid] = c; red_f[tid] = s;
    __syncthreads();
    for (int off = 128; off; off >>= 1) {
        if (tid < off) { red_u[tid] += red_u[tid + off]; red_f[tid] += red_f[tid + off]; }
        __syncthreads();
    }
    const unsigned ctot = red_u[0];
    const float sall = red_f[0];
    __syncthreads();

    if (ctot <= KSEL) {
        // every contributing element is among the K smallest
        if (tid == 0) rl[row] = sall;
        return;
    }

    // Radix-select the K-th smallest bit pattern (MSB-first, 8-bit digits)
    unsigned prefix = 0;
    unsigned remk = KSEL;
#pragma unroll
    for (int pass = 0; pass < 4; pass++) {
        const int shift = 24 - 8 * pass;
        hist[tid] = 0;
        __syncthreads();
        const unsigned pmask = (pass == 0) ? 0u : (0xFFFFFFFFu << (shift + 8));
        for (int i = tid; i < BDIM; i += 256) {
            unsigned b = __float_as_uint(vals[i]);
            if ((b & pmask) == prefix) atomicAdd(&hist[(b >> shift) & 255], 1u);
        }
        __syncthreads();
        if (tid == 0) {
            unsigned cum = 0;
            int d = 0;
            for (; d < 256; d++) {
                cum += hist[d];
                if (cum >= remk) break;
            }
            s_prefix = prefix | ((unsigned)d << shift);
            s_remk = remk - (cum - hist[d]);
        }
        __syncthreads();
        prefix = s_prefix;
        remk = s_remk;
        __syncthreads();
    }
    const float theta = __uint_as_float(prefix);

    // Sum strictly-below-theta, count below-theta; ties at theta fill to K
    unsigned cl = 0;
    float sl = 0.0f;
    for (int i = tid; i < BDIM; i += 256) {
        float v = vals[i];
        if (v < theta) { cl++; sl += v; }
    }
    red_u[tid] = cl; red_f[tid] = sl;
    __syncthreads();
    for (int off = 128; off; off >>= 1) {
        if (tid < off) { red_u[tid] += red_u[tid + off]; red_f[tid] += red_f[tid + off]; }
        __syncthreads();
    }
    if (tid == 0) {
        const unsigned cltot = red_u[0];
        const float sltot = red_f[0];
        // loss = K*t - (sum of K smallest) ; K smallest = all below theta + (K-cl) copies of theta
        rl[row] = (float)KSEL * t - sltot - (float)(KSEL - cltot) * theta;
    }
}

// ---------------------------------------------------------------------------
// Deterministic final reduction: out[0]=loss_xy, out[1]=loss_yx
// ---------------------------------------------------------------------------
__global__ void finalize_kernel(float* __restrict__ out) {
    __shared__ float sm[256];
    for (int which = 0; which < 2; which++) {
        float s = 0.0f;
        for (int i = threadIdx.x; i < BDIM; i += 256) s += g_rl[which * BDIM + i];
        sm[threadIdx.x] = s;
        __syncthreads();
        for (int off = 128; off; off >>= 1) {
            if (threadIdx.x < off) sm[threadIdx.x] += sm[threadIdx.x + off];
            __syncthreads();
        }
        if (threadIdx.x == 0)
            out[which] = sm[0] / ((float)BDIM * (float)KSEL);
        __syncthreads();
    }
}

// ---------------------------------------------------------------------------
extern "C" void kernel_launch(void* const* d_in, const int* in_sizes, int n_in,
                              void* d_out, int out_size) {
    const float* X = (const float*)d_in[0];
    const float* Y = (const float*)d_in[1];
    float* out = (float*)d_out;

    norms_kernel<<<dim3(BDIM, 2), 256>>>(X, Y);
    gemm_dist_kernel<<<dim3(32, 32), 256>>>(X, Y);
    transpose_kernel<<<dim3(128, 128), dim3(32, 8)>>>();
    select_kernel<<<dim3(BDIM, 2), 256>>>();
    finalize_kernel<<<1, 256>>>(out);
}

// round 3
// speedup vs baseline: 2.9134x; 2.9134x over previous
#include <cuda_runtime.h>
#include <math.h>
#include <stdint.h>

#define BDIM 4096
#define DDIM 1024
#define KSEL 1024
#define EPSV 1e-6f
#define MARGINV 0.5f
#define BIGV 1.0e6f

// ---------------- scratch (device globals; allocation-free) ----------------
__device__ float g_dist[(size_t)BDIM * BDIM];   // 64 MB
__device__ float g_distT[(size_t)BDIM * BDIM];  // 64 MB
__device__ float g_xr[(size_t)BDIM * DDIM];     // tf32-rounded X (16 MB)
__device__ float g_yr[(size_t)BDIM * DDIM];     // tf32-rounded Y (16 MB)
__device__ float g_nx[BDIM];
__device__ float g_ny[BDIM];
__device__ float g_sy[BDIM];
__device__ float g_rl[2 * BDIM];

// ---------------- helpers ----------------
__device__ __forceinline__ uint32_t smem_u32(const void* p) {
    uint32_t a;
    asm("{ .reg .u64 t; cvta.to.shared.u64 t, %1; cvt.u32.u64 %0, t; }" : "=r"(a) : "l"(p));
    return a;
}
__device__ __forceinline__ void cp16(void* dst, const void* src) {
    uint32_t d = smem_u32(dst);
    asm volatile("cp.async.cg.shared.global [%0], [%1], 16;" :: "r"(d), "l"(src));
}
#define CP_COMMIT() asm volatile("cp.async.commit_group;")
#define CP_WAIT1()  asm volatile("cp.async.wait_group 1;")

__device__ __forceinline__ float tf32_rna(float v) {
    uint32_t r;
    asm("cvt.rna.tf32.f32 %0, %1;" : "=r"(r) : "f"(v));
    return __uint_as_float(r);
}

__device__ __forceinline__ void mma_tf32(float* c, const uint32_t* a, const uint32_t* b) {
    asm volatile(
        "mma.sync.aligned.m16n8k8.row.col.f32.tf32.tf32.f32 "
        "{%0,%1,%2,%3}, {%4,%5,%6,%7}, {%8,%9}, {%0,%1,%2,%3};"
        : "+f"(c[0]), "+f"(c[1]), "+f"(c[2]), "+f"(c[3])
        : "r"(a[0]), "r"(a[1]), "r"(a[2]), "r"(a[3]), "r"(b[0]), "r"(b[1]));
}

// ---------------- GEMM config ----------------
#define BM 128
#define BN 128
#define BK 32
#define PITCH 36                      // floats; 144B rows: 16B-aligned, conflict-free frags
#define STAGE_FLOATS (2 * 128 * PITCH)  // A + B per stage = 9216 floats
#define GEMM_SMEM (2 * STAGE_FLOATS * 4)  // 73728 bytes

// ---------------------------------------------------------------------------
// Norms + tf32 pre-rounding:
//   nx[i]=||x_i+eps||^2 (fp32), ny[j]=||y_j||^2, sy[j]=sum(y_j);
//   g_xr = rna_tf32(X), g_yr = rna_tf32(Y)
// ---------------------------------------------------------------------------
__global__ void norms_kernel(const float* __restrict__ X, const float* __restrict__ Y) {
    __shared__ float s1[256], s2[256];
    const int row = blockIdx.x;
    const int isY = blockIdx.y;
    const float* p = (isY ? Y : X) + (size_t)row * DDIM;
    float* pr = (isY ? g_yr : g_xr) + (size_t)row * DDIM;
    float a = 0.0f, b = 0.0f;
    for (int i = threadIdx.x; i < DDIM; i += 256) {
        float v = p[i];
        pr[i] = tf32_rna(v);
        if (isY) { a += v * v; b += v; }
        else     { float ve = v + EPSV; a += ve * ve; }
    }
    s1[threadIdx.x] = a; s2[threadIdx.x] = b;
    __syncthreads();
    for (int off = 128; off; off >>= 1) {
        if (threadIdx.x < off) { s1[threadIdx.x] += s1[threadIdx.x + off];
                                 s2[threadIdx.x] += s2[threadIdx.x + off]; }
        __syncthreads();
    }
    if (threadIdx.x == 0) {
        if (isY) { g_ny[row] = s1[0]; g_sy[row] = s2[0]; }
        else     { g_nx[row] = s1[0]; }
    }
}

// ---------------------------------------------------------------------------
// tf32 mma.sync GEMM + distance epilogue (writes dist AND distT).
// 128x128 tile/CTA, 8 warps (4x2), warp tile 32x64, cp.async double buffer.
// ---------------------------------------------------------------------------
__device__ __forceinline__ void issue_stage(float* sA, float* sB,
                                            const float* gA, const float* gB, int tid) {
#pragma unroll
    for (int i = 0; i < 4; i++) {
        const int idx = tid + i * 256;      // 0..1023
        const int r = idx >> 3;             // row 0..127
        const int c = (idx & 7) * 4;        // float col 0,4,..,28
        cp16(sA + r * PITCH + c, gA + (size_t)r * DDIM + c);
        cp16(sB + r * PITCH + c, gB + (size_t)r * DDIM + c);
    }
}

__global__ void __launch_bounds__(256, 2) gemm_mma_kernel() {
    extern __shared__ float smf[];
    const int tid = threadIdx.x;
    const int wid = tid >> 5;
    const int lane = tid & 31;
    const int wm = wid & 3;          // warp row 0..3  (32 rows each)
    const int wn = wid >> 2;         // warp col 0..1  (64 cols each)
    const int g = lane >> 2;         // 0..7
    const int t = lane & 3;          // 0..3
    const int bi = blockIdx.y * BM;
    const int bj = blockIdx.x * BN;

    const float* gA = g_xr + (size_t)bi * DDIM;
    const float* gB = g_yr + (size_t)bj * DDIM;

    float acc[2][8][4];
#pragma unroll
    for (int mi = 0; mi < 2; mi++)
#pragma unroll
        for (int ni = 0; ni < 8; ni++)
#pragma unroll
            for (int e = 0; e < 4; e++) acc[mi][ni][e] = 0.0f;

    // prologue: two stages in flight
    issue_stage(smf, smf + 128 * PITCH, gA, gB, tid);
    CP_COMMIT();
    issue_stage(smf + STAGE_FLOATS, smf + STAGE_FLOATS + 128 * PITCH,
                gA + BK, gB + BK, tid);
    CP_COMMIT();

    const int NCHUNK = DDIM / BK;    // 32
    for (int c = 0; c < NCHUNK; c++) {
        const int buf = c & 1;
        CP_WAIT1();
        __syncthreads();
        const uint32_t* sA = (const uint32_t*)(smf + buf * STAGE_FLOATS);
        const uint32_t* sB = sA + 128 * PITCH;

#pragma unroll
        for (int ks = 0; ks < 4; ks++) {
            const int k0 = ks * 8;
            uint32_t a[2][4], b[8][2];
#pragma unroll
            for (int mi = 0; mi < 2; mi++) {
                const int r0 = wm * 32 + mi * 16;
                a[mi][0] = sA[(r0 + g) * PITCH + k0 + t];
                a[mi][1] = sA[(r0 + g + 8) * PITCH + k0 + t];
                a[mi][2] = sA[(r0 + g) * PITCH + k0 + t + 4];
                a[mi][3] = sA[(r0 + g + 8) * PITCH + k0 + t + 4];
            }
#pragma unroll
            for (int ni = 0; ni < 8; ni++) {
                const int c0 = wn * 64 + ni * 8;
                b[ni][0] = sB[(c0 + g) * PITCH + k0 + t];
                b[ni][1] = sB[(c0 + g) * PITCH + k0 + t + 4];
            }
#pragma unroll
            for (int mi = 0; mi < 2; mi++)
#pragma unroll
                for (int ni = 0; ni < 8; ni++)
                    mma_tf32(acc[mi][ni], a[mi], b[ni]);
        }
        __syncthreads();
        if (c + 2 < NCHUNK)
            issue_stage((float*)(smf + buf * STAGE_FLOATS),
                        (float*)(smf + buf * STAGE_FLOATS + 128 * PITCH),
                        gA + (c + 2) * BK, gB + (c + 2) * BK, tid);
        CP_COMMIT();
    }

    // -------- epilogue: regs -> smem tile (pitch 129) -> dist & distT --------
    __syncthreads();
    float* tile = smf;                       // 128 x 129
    float* nx_s = smf + 128 * 129;           // +16512
    float* ny_s = nx_s + 128;
    float* sy_s = ny_s + 128;
    if (tid < 128) {
        nx_s[tid] = g_nx[bi + tid];
        ny_s[tid] = g_ny[bj + tid];
        sy_s[tid] = g_sy[bj + tid];
    }
    __syncthreads();

#pragma unroll
    for (int mi = 0; mi < 2; mi++) {
        const int r0 = wm * 32 + mi * 16 + g;
#pragma unroll
        for (int ni = 0; ni < 8; ni++) {
            const int c0 = wn * 64 + ni * 8 + 2 * t;
#pragma unroll
            for (int e = 0; e < 4; e++) {
                const int row = r0 + (e >> 1) * 8;
                const int col = c0 + (e & 1);
                float sq = nx_s[row] + ny_s[col] - 2.0f * acc[mi][ni][e]
                           - 2.0f * EPSV * sy_s[col];
                tile[row * 129 + col] = sqrtf(fmaxf(sq, 0.0f));
            }
        }
    }
    __syncthreads();

    // dist: coalesced float4 row writes
    for (int i = tid; i < 128 * 32; i += 256) {
        const int rr = i >> 5;
        const int c4 = (i & 31) << 2;
        float4 v;
        v.x = tile[rr * 129 + c4 + 0];
        v.y = tile[rr * 129 + c4 + 1];
        v.z = tile[rr * 129 + c4 + 2];
        v.w = tile[rr * 129 + c4 + 3];
        *(float4*)&g_dist[(size_t)(bi + rr) * BDIM + bj + c4] = v;
    }
    // distT: conflict-free column reads (pitch 129), coalesced row writes
    for (int i = tid; i < 128 * 128; i += 256) {
        const int rr = i & 127;
        const int cc = i >> 7;
        g_distT[(size_t)(bj + cc) * BDIM + bi + rr] = tile[rr * 129 + cc];
    }
}

// ---------------------------------------------------------------------------
// Per-row loss with exact K-th order statistic (radix select on float bits).
// grid (BDIM, 2): y=0 rows of dist (loss_xy), y=1 rows of distT (loss_yx).
// ---------------------------------------------------------------------------
__global__ void __launch_bounds__(256) select_kernel() {
    __shared__ float vals[BDIM];
    __shared__ unsigned hist[256];
    __shared__ float red_f[256];
    __shared__ unsigned red_u[256];
    __shared__ float s_t;
    __shared__ unsigned s_prefix, s_remk;

    const int row = blockIdx.x;
    const int tid = threadIdx.x;
    const float* mat = blockIdx.y ? g_distT : g_dist;
    float* rl = g_rl + blockIdx.y * BDIM;
    const float4* rp4 = (const float4*)(mat + (size_t)row * BDIM);
    float4* v4 = (float4*)vals;

    for (int i = tid; i < BDIM / 4; i += 256) v4[i] = rp4[i];
    __syncthreads();
    if (tid == 0) {
        s_t = MARGINV + vals[row];
        vals[row] = BIGV;
    }
    __syncthreads();
    const float t = s_t;

    unsigned c = 0; float s = 0.0f;
    for (int i = tid; i < BDIM; i += 256) {
        float v = vals[i];
        if (v < t) { c++; s += t - v; }
    }
    red_u[tid] = c; red_f[tid] = s;
    __syncthreads();
    for (int off = 128; off; off >>= 1) {
        if (tid < off) { red_u[tid] += red_u[tid + off]; red_f[tid] += red_f[tid + off]; }
        __syncthreads();
    }
    const unsigned ctot = red_u[0];
    const float sall = red_f[0];
    __syncthreads();

    if (ctot <= KSEL) {
        if (tid == 0) rl[row] = sall;
        return;
    }

    unsigned prefix = 0, remk = KSEL;
#pragma unroll
    for (int pass = 0; pass < 4; pass++) {
        const int shift = 24 - 8 * pass;
        hist[tid] = 0;
        __syncthreads();
        const unsigned pmask = (pass == 0) ? 0u : (0xFFFFFFFFu << (shift + 8));
        for (int i = tid; i < BDIM; i += 256) {
            unsigned b = __float_as_uint(vals[i]);
            if ((b & pmask) == prefix) atomicAdd(&hist[(b >> shift) & 255], 1u);
        }
        __syncthreads();
        if (tid == 0) {
            unsigned cum = 0; int d = 0;
            for (; d < 256; d++) { cum += hist[d]; if (cum >= remk) break; }
            s_prefix = prefix | ((unsigned)d << shift);
            s_remk = remk - (cum - hist[d]);
        }
        __syncthreads();
        prefix = s_prefix; remk = s_remk;
        __syncthreads();
    }
    const float theta = __uint_as_float(prefix);

    unsigned cl = 0; float sl = 0.0f;
    for (int i = tid; i < BDIM; i += 256) {
        float v = vals[i];
        if (v < theta) { cl++; sl += v; }
    }
    red_u[tid] = cl; red_f[tid] = sl;
    __syncthreads();
    for (int off = 128; off; off >>= 1) {
        if (tid < off) { red_u[tid] += red_u[tid + off]; red_f[tid] += red_f[tid + off]; }
        __syncthreads();
    }
    if (tid == 0) {
        rl[row] = (float)KSEL * t - red_f[0] - (float)(KSEL - red_u[0]) * theta;
    }
}

__global__ void finalize_kernel(float* __restrict__ out) {
    __shared__ float sm[256];
    for (int which = 0; which < 2; which++) {
        float s = 0.0f;
        for (int i = threadIdx.x; i < BDIM; i += 256) s += g_rl[which * BDIM + i];
        sm[threadIdx.x] = s;
        __syncthreads();
        for (int off = 128; off; off >>= 1) {
            if (threadIdx.x < off) sm[threadIdx.x] += sm[threadIdx.x + off];
            __syncthreads();
        }
        if (threadIdx.x == 0) out[which] = sm[0] / ((float)BDIM * (float)KSEL);
        __syncthreads();
    }
}

// ---------------------------------------------------------------------------
extern "C" void kernel_launch(void* const* d_in, const int* in_sizes, int n_in,
                              void* d_out, int out_size) {
    const float* X = (const float*)d_in[0];
    const float* Y = (const float*)d_in[1];
    float* out = (float*)d_out;

    cudaFuncSetAttribute(gemm_mma_kernel, cudaFuncAttributeMaxDynamicSharedMemorySize,
                         GEMM_SMEM);

    norms_kernel<<<dim3(BDIM, 2), 256>>>(X, Y);
    gemm_mma_kernel<<<dim3(BDIM / BN, BDIM / BM), 256, GEMM_SMEM>>>();
    select_kernel<<<dim3(BDIM, 2), 256>>>();
    finalize_kernel<<<1, 256>>>(out);
}